// round 7
// baseline (speedup 1.0000x reference)
#include <cuda_runtime.h>
#include <cuda_fp16.h>
#include <cstdint>

// ---------------------------------------------------------------------------
// FP8Linear: out[M,N] = x[M,K] @ (qweight*scales)^T + bias
// M=8192, N=16384, K=4096, group=128.
// R6: CTA tile 256x128 (8 warps, 4m x 2n, warp tile 64x64 kept from R5).
// Cuts total L2 operand traffic 16GB -> 12GB; 1 CTA/SM, 96KB smem.
// ---------------------------------------------------------------------------

#define M_ALL 8192
#define N_ALL 16384
#define K_ALL 4096
#define TM 256
#define TN 128
#define TK 32
#define THREADS 256
#define NKT (K_ALL / TK)              // 128
#define NSTAGES 4
#define STAGE_U4 1536                 // A0 512 + A1 512 + B 512 uint4
#define STAGE_BYTES (STAGE_U4 * 16)   // 24576
#define SMEM_TOTAL (NSTAGES * STAGE_BYTES)  // 98304

// Packed operand scratch (fragment-major, fp16) -- layout unchanged from R4/R5.
// A' chunk (mb,kt,it,s,lane): regs x/y/z/w = {m=g,k0},{m=g+8,k0},{m=g,k0+8},{m=g+8,k0+8}
//   chunk id = mb*65536 + kt*512 + it*64 + s*32 + lane   (mb: 128-row block)
// B' chunk (nb,kt,jt,lane):   regs x/y/z/w = (s0,r0),(s0,r1),(s1,r0),(s1,r1)
//   chunk id = nb*65536 + kt*512 + jt*32 + lane
__device__ uint4 Xp[64ull * 128 * 8 * 2 * 32];     //  64 MB
__device__ uint4 Wp[128ull * 128 * 16 * 32];       // 128 MB

// ---------------- helpers ----------------
__device__ __forceinline__ void cp_async16(uint32_t smem_dst, const void* gsrc) {
    asm volatile("cp.async.cg.shared.global [%0], [%1], 16;"
                 :: "r"(smem_dst), "l"(__cvta_generic_to_global(gsrc))
                 : "memory");
}
#define CP_COMMIT() asm volatile("cp.async.commit_group;" ::: "memory")
#define CP_WAIT2()  asm volatile("cp.async.wait_group 2;" ::: "memory")

__device__ __forceinline__ void mma_f16(float* c, const uint32_t* a,
                                        uint32_t b0, uint32_t b1) {
    asm volatile(
        "mma.sync.aligned.m16n8k16.row.col.f32.f16.f16.f32 "
        "{%0,%1,%2,%3}, {%4,%5,%6,%7}, {%8,%9}, {%0,%1,%2,%3};"
        : "+f"(c[0]), "+f"(c[1]), "+f"(c[2]), "+f"(c[3])
        : "r"(a[0]), "r"(a[1]), "r"(a[2]), "r"(a[3]), "r"(b0), "r"(b1));
}

__device__ __forceinline__ uint32_t h2(float lo, float hi) {
    __half2 h = __floats2half2_rn(lo, hi);
    return *(uint32_t*)&h;
}

// ---------------- prep kernels (unchanged) ----------------
// cid fields: lane[0:5) s[5] it[6:9) kt[9:16) mb[16:22)
__global__ void __launch_bounds__(256)
prep_x_kernel(const float* __restrict__ X) {
    uint32_t cid = blockIdx.x * 256 + threadIdx.x;
    int lane = cid & 31;
    int s    = (cid >> 5) & 1;
    int it   = (cid >> 6) & 7;
    int kt   = (cid >> 9) & 127;
    int mb   = cid >> 16;
    int g = lane >> 2, tig = lane & 3;
    int m0 = mb * 128 + it * 16 + g;
    int k0 = kt * 32 + s * 16 + 2 * tig;
    const float* p0 = X + (size_t)m0 * K_ALL + k0;
    const float* p1 = X + (size_t)(m0 + 8) * K_ALL + k0;
    float2 v0 = *(const float2*)(p0);
    float2 v1 = *(const float2*)(p1);
    float2 v2 = *(const float2*)(p0 + 8);
    float2 v3 = *(const float2*)(p1 + 8);
    uint4 out;
    out.x = h2(v0.x, v0.y);
    out.y = h2(v1.x, v1.y);
    out.z = h2(v2.x, v2.y);
    out.w = h2(v3.x, v3.y);
    Xp[cid] = out;
}

// cid fields: lane[0:5) jt[5:9) kt[9:16) nb[16:23)
__global__ void __launch_bounds__(256)
prep_w_kernel(const float* __restrict__ W, const float* __restrict__ S) {
    uint32_t cid = blockIdx.x * 256 + threadIdx.x;
    int lane = cid & 31;
    int jt   = (cid >> 5) & 15;
    int kt   = (cid >> 9) & 127;
    int nb   = cid >> 16;
    int g = lane >> 2, tig = lane & 3;
    int n  = nb * 128 + jt * 8 + g;
    int kb = kt * 32 + 2 * tig;
    float sc = __ldg(S + (size_t)n * 32 + (kt >> 2));
    const float* p = W + (size_t)n * K_ALL + kb;
    float2 v0 = *(const float2*)(p);
    float2 v1 = *(const float2*)(p + 8);
    float2 v2 = *(const float2*)(p + 16);
    float2 v3 = *(const float2*)(p + 24);
    uint4 out;
    out.x = h2(v0.x * sc, v0.y * sc);
    out.y = h2(v1.x * sc, v1.y * sc);
    out.z = h2(v2.x * sc, v2.y * sc);
    out.w = h2(v3.x * sc, v3.y * sc);
    Wp[cid] = out;
}

// ---------------- GEMM ----------------
extern __shared__ __align__(1024) char smem_raw[];

// stage layout (uint4): [0:512) A block0, [512:1024) A block1, [1024:1536) B
__device__ __forceinline__ void load_tile(const uint4* __restrict__ Abase,
                                          const uint4* __restrict__ Bbase,
                                          int kt, char* stage, int tid) {
    uint32_t sb = (uint32_t)__cvta_generic_to_shared(stage);
    const uint4* A0 = Abase + kt * 512;
    const uint4* A1 = A0 + 65536;
    const uint4* B  = Bbase + kt * 512;
    cp_async16(sb + tid * 16,              A0 + tid);
    cp_async16(sb + (tid + 256) * 16,      A0 + tid + 256);
    cp_async16(sb + (tid + 512) * 16,      A1 + tid);
    cp_async16(sb + (tid + 768) * 16,      A1 + tid + 256);
    cp_async16(sb + (tid + 1024) * 16,     B + tid);
    cp_async16(sb + (tid + 1280) * 16,     B + tid + 256);
}

__global__ void __launch_bounds__(THREADS, 1)
fp8linear_hmma_kernel(const float* __restrict__ BIAS,
                      float* __restrict__ OUT) {
    const int tid = threadIdx.x;
    const int lane = tid & 31;
    const int wid = tid >> 5;      // 0..7
    const int wm = wid & 3;        // 4 x 64 rows
    const int wn = wid >> 2;       // 2 x 64 cols
    const int g = lane >> 2;
    const int tig = lane & 3;
    const int ab = wm >> 1;        // A smem block 0/1
    const int itbase = (wm & 1) * 4;

    // rasterization: tiles_m=32, tiles_n=128, GROUP_M=16
    int pid = blockIdx.x;
    int group = pid >> 11;
    int pid_loc = pid & 2047;
    int pid_m = group * 16 + (pid_loc & 15);
    int pid_n = pid_loc >> 4;

    const uint4* Abase = Xp + (size_t)pid_m * 2 * 65536;  // two 128-row blocks
    const uint4* Bbase = Wp + (size_t)pid_n * 65536;

    float acc[4][8][4];
    #pragma unroll
    for (int i = 0; i < 4; i++)
        #pragma unroll
        for (int j = 0; j < 8; j++)
            #pragma unroll
            for (int q = 0; q < 4; q++) acc[i][j][q] = 0.0f;

    #pragma unroll
    for (int p = 0; p < 3; p++) {
        load_tile(Abase, Bbase, p, smem_raw + p * STAGE_BYTES, tid);
        CP_COMMIT();
    }

    for (int kt = 0; kt < NKT; kt++) {
        CP_WAIT2();
        __syncthreads();
        if (kt + 3 < NKT)
            load_tile(Abase, Bbase, kt + 3,
                      smem_raw + ((kt + 3) & 3) * STAGE_BYTES, tid);
        CP_COMMIT();

        const char* stg = smem_raw + (kt & 3) * STAGE_BYTES;
        const uint4* As = (const uint4*)stg + ab * 512;
        const uint4* Bs = (const uint4*)stg + 1024;

        uint4 bfr[8];
        #pragma unroll
        for (int j = 0; j < 8; j++)
            bfr[j] = Bs[(wn * 8 + j) * 32 + lane];

        #pragma unroll
        for (int s = 0; s < 2; s++) {
            uint4 afr[4];
            #pragma unroll
            for (int i = 0; i < 4; i++)
                afr[i] = As[((itbase + i) * 2 + s) * 32 + lane];
            #pragma unroll
            for (int i = 0; i < 4; i++) {
                #pragma unroll
                for (int j = 0; j < 8; j++) {
                    uint32_t b0 = s ? bfr[j].z : bfr[j].x;
                    uint32_t b1 = s ? bfr[j].w : bfr[j].y;
                    mma_f16(acc[i][j], (const uint32_t*)&afr[i], b0, b1);
                }
            }
        }
    }

    // ---------------- epilogue: bias + store ----------------
    #pragma unroll
    for (int j = 0; j < 8; j++) {
        int col = pid_n * TN + wn * 64 + j * 8 + tig * 2;
        float2 bb = *(const float2*)(BIAS + col);
        #pragma unroll
        for (int i = 0; i < 4; i++) {
            int row0 = pid_m * TM + wm * 64 + i * 16 + g;
            float2 o0, o1;
            o0.x = acc[i][j][0] + bb.x;
            o0.y = acc[i][j][1] + bb.y;
            o1.x = acc[i][j][2] + bb.x;
            o1.y = acc[i][j][3] + bb.y;
            *(float2*)(OUT + (size_t)row0 * N_ALL + col) = o0;
            *(float2*)(OUT + (size_t)(row0 + 8) * N_ALL + col) = o1;
        }
    }
}

// ---------------- launch ----------------
extern "C" void kernel_launch(void* const* d_in, const int* in_sizes, int n_in,
                              void* d_out, int out_size) {
    const float* x = (const float*)d_in[0];      // [4,2048,4096]
    const float* qw = (const float*)d_in[1];     // [16384,4096]
    const float* sc = (const float*)d_in[2];     // [16384,32]
    const float* bias = (const float*)d_in[3];   // [16384]
    float* out = (float*)d_out;                  // [4,2048,16384]

    prep_x_kernel<<<4194304 / 256, 256>>>(x);
    prep_w_kernel<<<8388608 / 256, 256>>>(qw, sc);

    cudaFuncSetAttribute(fp8linear_hmma_kernel,
                         cudaFuncAttributeMaxDynamicSharedMemorySize, SMEM_TOTAL);
    int grid = (M_ALL / TM) * (N_ALL / TN);      // 32 * 128 = 4096
    fp8linear_hmma_kernel<<<grid, THREADS, SMEM_TOTAL>>>(bias, out);
}

// round 8
// speedup vs baseline: 1.2201x; 1.2201x over previous
#include <cuda_runtime.h>
#include <cuda_fp16.h>
#include <cstdint>

// ---------------------------------------------------------------------------
// FP8Linear: out[M,N] = x[M,K] @ (qweight*scales)^T + bias
// M=8192, N=16384, K=4096, group=128.
// R8: R5 shape (CTA 128x128, 4 warps, warp tile 64x64, 2 CTAs/SM) with
// K-step per pipeline stage doubled to 64 (3 stages x 32KB): half the
// barriers/waits of R5. R6's 256x128 tile reverted (1 CTA/SM killed overlap).
// ---------------------------------------------------------------------------

#define M_ALL 8192
#define N_ALL 16384
#define K_ALL 4096
#define TM 128
#define TN 128
#define THREADS 128
#define NIT 64                          // outer iters, 64 k each
#define NSTAGES 3
#define STAGE_U4 2048                   // A 1024 + B 1024 uint4
#define STAGE_BYTES (STAGE_U4 * 16)     // 32768
#define SMEM_TOTAL (NSTAGES * STAGE_BYTES)  // 98304

// Packed operand scratch (fragment-major, fp16) -- layout unchanged since R4.
// A' chunk (mb,kt,it,s,lane): regs x/y/z/w = {m=g,k0},{m=g+8,k0},{m=g,k0+8},{m=g+8,k0+8}
//   chunk id = mb*65536 + kt*512 + it*64 + s*32 + lane
// B' chunk (nb,kt,jt,lane):   regs x/y/z/w = (s0,r0),(s0,r1),(s1,r0),(s1,r1)
//   chunk id = nb*65536 + kt*512 + jt*32 + lane
__device__ uint4 Xp[64ull * 128 * 8 * 2 * 32];     //  64 MB
__device__ uint4 Wp[128ull * 128 * 16 * 32];       // 128 MB

// ---------------- helpers ----------------
__device__ __forceinline__ void cp_async16(uint32_t smem_dst, const void* gsrc) {
    asm volatile("cp.async.cg.shared.global [%0], [%1], 16;"
                 :: "r"(smem_dst), "l"(__cvta_generic_to_global(gsrc))
                 : "memory");
}
#define CP_COMMIT() asm volatile("cp.async.commit_group;" ::: "memory")
#define CP_WAIT1()  asm volatile("cp.async.wait_group 1;" ::: "memory")

__device__ __forceinline__ void mma_f16(float* c, const uint32_t* a,
                                        uint32_t b0, uint32_t b1) {
    asm volatile(
        "mma.sync.aligned.m16n8k16.row.col.f32.f16.f16.f32 "
        "{%0,%1,%2,%3}, {%4,%5,%6,%7}, {%8,%9}, {%0,%1,%2,%3};"
        : "+f"(c[0]), "+f"(c[1]), "+f"(c[2]), "+f"(c[3])
        : "r"(a[0]), "r"(a[1]), "r"(a[2]), "r"(a[3]), "r"(b0), "r"(b1));
}

__device__ __forceinline__ uint32_t h2(float lo, float hi) {
    __half2 h = __floats2half2_rn(lo, hi);
    return *(uint32_t*)&h;
}

// ---------------- prep kernels (unchanged) ----------------
// cid fields: lane[0:5) s[5] it[6:9) kt[9:16) mb[16:22)
__global__ void __launch_bounds__(256)
prep_x_kernel(const float* __restrict__ X) {
    uint32_t cid = blockIdx.x * 256 + threadIdx.x;
    int lane = cid & 31;
    int s    = (cid >> 5) & 1;
    int it   = (cid >> 6) & 7;
    int kt   = (cid >> 9) & 127;
    int mb   = cid >> 16;
    int g = lane >> 2, tig = lane & 3;
    int m0 = mb * 128 + it * 16 + g;
    int k0 = kt * 32 + s * 16 + 2 * tig;
    const float* p0 = X + (size_t)m0 * K_ALL + k0;
    const float* p1 = X + (size_t)(m0 + 8) * K_ALL + k0;
    float2 v0 = *(const float2*)(p0);
    float2 v1 = *(const float2*)(p1);
    float2 v2 = *(const float2*)(p0 + 8);
    float2 v3 = *(const float2*)(p1 + 8);
    uint4 out;
    out.x = h2(v0.x, v0.y);
    out.y = h2(v1.x, v1.y);
    out.z = h2(v2.x, v2.y);
    out.w = h2(v3.x, v3.y);
    Xp[cid] = out;
}

// cid fields: lane[0:5) jt[5:9) kt[9:16) nb[16:23)
__global__ void __launch_bounds__(256)
prep_w_kernel(const float* __restrict__ W, const float* __restrict__ S) {
    uint32_t cid = blockIdx.x * 256 + threadIdx.x;
    int lane = cid & 31;
    int jt   = (cid >> 5) & 15;
    int kt   = (cid >> 9) & 127;
    int nb   = cid >> 16;
    int g = lane >> 2, tig = lane & 3;
    int n  = nb * 128 + jt * 8 + g;
    int kb = kt * 32 + 2 * tig;
    float sc = __ldg(S + (size_t)n * 32 + (kt >> 2));
    const float* p = W + (size_t)n * K_ALL + kb;
    float2 v0 = *(const float2*)(p);
    float2 v1 = *(const float2*)(p + 8);
    float2 v2 = *(const float2*)(p + 16);
    float2 v3 = *(const float2*)(p + 24);
    uint4 out;
    out.x = h2(v0.x * sc, v0.y * sc);
    out.y = h2(v1.x * sc, v1.y * sc);
    out.z = h2(v2.x * sc, v2.y * sc);
    out.w = h2(v3.x * sc, v3.y * sc);
    Wp[cid] = out;
}

// ---------------- GEMM ----------------
extern __shared__ __align__(1024) char smem_raw[];

// stage layout (uint4): [0:1024) A (kt even then odd), [1024:2048) B
__device__ __forceinline__ void load_stage(const uint4* __restrict__ Abase,
                                           const uint4* __restrict__ Bbase,
                                           int o, char* stage, int tid) {
    uint32_t sb = (uint32_t)__cvta_generic_to_shared(stage);
    const uint4* A = Abase + o * 1024;   // two consecutive kt blocks
    const uint4* B = Bbase + o * 1024;
    #pragma unroll
    for (int i = 0; i < 8; i++)
        cp_async16(sb + (tid + i * THREADS) * 16, A + tid + i * THREADS);
    #pragma unroll
    for (int i = 0; i < 8; i++)
        cp_async16(sb + (tid + (8 + i) * THREADS) * 16, B + tid + i * THREADS);
}

__global__ void __launch_bounds__(THREADS, 2)
fp8linear_hmma_kernel(const float* __restrict__ BIAS,
                      float* __restrict__ OUT) {
    const int tid = threadIdx.x;
    const int lane = tid & 31;
    const int wid = tid >> 5;      // 0..3
    const int wm = wid & 1;        // 2 x 64 rows
    const int wn = wid >> 1;       // 2 x 64 cols
    const int g = lane >> 2;
    const int tig = lane & 3;

    // rasterization: GROUP_M=16
    int pid = blockIdx.x;
    int group = pid >> 11;
    int pid_loc = pid & 2047;
    int pid_m = group * 16 + (pid_loc & 15);
    int pid_n = pid_loc >> 4;

    const uint4* Abase = Xp + (size_t)pid_m * 65536;
    const uint4* Bbase = Wp + (size_t)pid_n * 65536;

    float acc[4][8][4];
    #pragma unroll
    for (int i = 0; i < 4; i++)
        #pragma unroll
        for (int j = 0; j < 8; j++)
            #pragma unroll
            for (int q = 0; q < 4; q++) acc[i][j][q] = 0.0f;

    #pragma unroll
    for (int p = 0; p < 2; p++) {
        load_stage(Abase, Bbase, p, smem_raw + p * STAGE_BYTES, tid);
        CP_COMMIT();
    }

    for (int o = 0; o < NIT; o++) {
        CP_WAIT1();
        __syncthreads();
        if (o + 2 < NIT)
            load_stage(Abase, Bbase, o + 2,
                       smem_raw + ((o + 2) % NSTAGES) * STAGE_BYTES, tid);
        CP_COMMIT();

        const char* stg = smem_raw + (o % NSTAGES) * STAGE_BYTES;

        #pragma unroll
        for (int h = 0; h < 2; h++) {     // two kt halves per stage
            const uint4* As = (const uint4*)stg + h * 512;
            const uint4* Bs = (const uint4*)stg + 1024 + h * 512;

            uint4 bfr[8];
            #pragma unroll
            for (int j = 0; j < 8; j++)
                bfr[j] = Bs[(wn * 8 + j) * 32 + lane];

            #pragma unroll
            for (int s = 0; s < 2; s++) {
                uint4 afr[4];
                #pragma unroll
                for (int i = 0; i < 4; i++)
                    afr[i] = As[((wm * 4 + i) * 2 + s) * 32 + lane];
                #pragma unroll
                for (int i = 0; i < 4; i++) {
                    #pragma unroll
                    for (int j = 0; j < 8; j++) {
                        uint32_t b0 = s ? bfr[j].z : bfr[j].x;
                        uint32_t b1 = s ? bfr[j].w : bfr[j].y;
                        mma_f16(acc[i][j], (const uint32_t*)&afr[i], b0, b1);
                    }
                }
            }
        }
    }

    // ---------------- epilogue: bias + store ----------------
    #pragma unroll
    for (int j = 0; j < 8; j++) {
        int col = pid_n * TN + wn * 64 + j * 8 + tig * 2;
        float2 bb = *(const float2*)(BIAS + col);
        #pragma unroll
        for (int i = 0; i < 4; i++) {
            int row0 = pid_m * TM + wm * 64 + i * 16 + g;
            float2 o0, o1;
            o0.x = acc[i][j][0] + bb.x;
            o0.y = acc[i][j][1] + bb.y;
            o1.x = acc[i][j][2] + bb.x;
            o1.y = acc[i][j][3] + bb.y;
            *(float2*)(OUT + (size_t)row0 * N_ALL + col) = o0;
            *(float2*)(OUT + (size_t)(row0 + 8) * N_ALL + col) = o1;
        }
    }
}

// ---------------- launch ----------------
extern "C" void kernel_launch(void* const* d_in, const int* in_sizes, int n_in,
                              void* d_out, int out_size) {
    const float* x = (const float*)d_in[0];      // [4,2048,4096]
    const float* qw = (const float*)d_in[1];     // [16384,4096]
    const float* sc = (const float*)d_in[2];     // [16384,32]
    const float* bias = (const float*)d_in[3];   // [16384]
    float* out = (float*)d_out;                  // [4,2048,16384]

    prep_x_kernel<<<4194304 / 256, 256>>>(x);
    prep_w_kernel<<<8388608 / 256, 256>>>(qw, sc);

    cudaFuncSetAttribute(fp8linear_hmma_kernel,
                         cudaFuncAttributeMaxDynamicSharedMemorySize, SMEM_TOTAL);
    int grid = (M_ALL / TM) * (N_ALL / TN);      // 8192
    fp8linear_hmma_kernel<<<grid, THREADS, SMEM_TOTAL>>>(bias, out);
}

// round 9
// speedup vs baseline: 1.3635x; 1.1175x over previous
#include <cuda_runtime.h>
#include <cuda_fp16.h>
#include <cstdint>

// ---------------------------------------------------------------------------
// FP8Linear: out[M,N] = x[M,K] @ (qweight*scales)^T + bias
// M=8192, N=16384, K=4096, group=128.
// R9: exact R5 shape (CTA 128x128, 4 warps, warp tile 64x64, 2 CTAs/SM,
// TK=32) with pipeline deepened 4 -> 6 stages (wait_group 4).
// R6 (256x128) and R8 (TK=64) both regressed; this keeps everything R5 won.
// ---------------------------------------------------------------------------

#define M_ALL 8192
#define N_ALL 16384
#define K_ALL 4096
#define TM 128
#define TN 128
#define TK 32
#define THREADS 128
#define NKT (K_ALL / TK)              // 128
#define NSTAGES 6
#define STAGE_BYTES 16384             // A 8KB + B 8KB (fp16)
#define SMEM_TOTAL (NSTAGES * STAGE_BYTES)  // 98304

// Packed operand scratch (fragment-major, fp16) -- layout unchanged since R4.
// A' chunk (mb,kt,it,s,lane): regs x/y/z/w = {m=g,k0},{m=g+8,k0},{m=g,k0+8},{m=g+8,k0+8}
//   chunk id = mb*65536 + kt*512 + it*64 + s*32 + lane
// B' chunk (nb,kt,jt,lane):   regs x/y/z/w = (s0,r0),(s0,r1),(s1,r0),(s1,r1)
//   chunk id = nb*65536 + kt*512 + jt*32 + lane
__device__ uint4 Xp[64ull * 128 * 8 * 2 * 32];     //  64 MB
__device__ uint4 Wp[128ull * 128 * 16 * 32];       // 128 MB

// ---------------- helpers ----------------
__device__ __forceinline__ void cp_async16(uint32_t smem_dst, const void* gsrc) {
    asm volatile("cp.async.cg.shared.global [%0], [%1], 16;"
                 :: "r"(smem_dst), "l"(__cvta_generic_to_global(gsrc))
                 : "memory");
}
#define CP_COMMIT() asm volatile("cp.async.commit_group;" ::: "memory")
#define CP_WAIT4()  asm volatile("cp.async.wait_group 4;" ::: "memory")

__device__ __forceinline__ void mma_f16(float* c, const uint32_t* a,
                                        uint32_t b0, uint32_t b1) {
    asm volatile(
        "mma.sync.aligned.m16n8k16.row.col.f32.f16.f16.f32 "
        "{%0,%1,%2,%3}, {%4,%5,%6,%7}, {%8,%9}, {%0,%1,%2,%3};"
        : "+f"(c[0]), "+f"(c[1]), "+f"(c[2]), "+f"(c[3])
        : "r"(a[0]), "r"(a[1]), "r"(a[2]), "r"(a[3]), "r"(b0), "r"(b1));
}

__device__ __forceinline__ uint32_t h2(float lo, float hi) {
    __half2 h = __floats2half2_rn(lo, hi);
    return *(uint32_t*)&h;
}

// ---------------- prep kernels (unchanged) ----------------
// cid fields: lane[0:5) s[5] it[6:9) kt[9:16) mb[16:22)
__global__ void __launch_bounds__(256)
prep_x_kernel(const float* __restrict__ X) {
    uint32_t cid = blockIdx.x * 256 + threadIdx.x;
    int lane = cid & 31;
    int s    = (cid >> 5) & 1;
    int it   = (cid >> 6) & 7;
    int kt   = (cid >> 9) & 127;
    int mb   = cid >> 16;
    int g = lane >> 2, tig = lane & 3;
    int m0 = mb * 128 + it * 16 + g;
    int k0 = kt * 32 + s * 16 + 2 * tig;
    const float* p0 = X + (size_t)m0 * K_ALL + k0;
    const float* p1 = X + (size_t)(m0 + 8) * K_ALL + k0;
    float2 v0 = *(const float2*)(p0);
    float2 v1 = *(const float2*)(p1);
    float2 v2 = *(const float2*)(p0 + 8);
    float2 v3 = *(const float2*)(p1 + 8);
    uint4 out;
    out.x = h2(v0.x, v0.y);
    out.y = h2(v1.x, v1.y);
    out.z = h2(v2.x, v2.y);
    out.w = h2(v3.x, v3.y);
    Xp[cid] = out;
}

// cid fields: lane[0:5) jt[5:9) kt[9:16) nb[16:23)
__global__ void __launch_bounds__(256)
prep_w_kernel(const float* __restrict__ W, const float* __restrict__ S) {
    uint32_t cid = blockIdx.x * 256 + threadIdx.x;
    int lane = cid & 31;
    int jt   = (cid >> 5) & 15;
    int kt   = (cid >> 9) & 127;
    int nb   = cid >> 16;
    int g = lane >> 2, tig = lane & 3;
    int n  = nb * 128 + jt * 8 + g;
    int kb = kt * 32 + 2 * tig;
    float sc = __ldg(S + (size_t)n * 32 + (kt >> 2));
    const float* p = W + (size_t)n * K_ALL + kb;
    float2 v0 = *(const float2*)(p);
    float2 v1 = *(const float2*)(p + 8);
    float2 v2 = *(const float2*)(p + 16);
    float2 v3 = *(const float2*)(p + 24);
    uint4 out;
    out.x = h2(v0.x * sc, v0.y * sc);
    out.y = h2(v1.x * sc, v1.y * sc);
    out.z = h2(v2.x * sc, v2.y * sc);
    out.w = h2(v3.x * sc, v3.y * sc);
    Wp[cid] = out;
}

// ---------------- GEMM ----------------
extern __shared__ __align__(1024) char smem_raw[];

__device__ __forceinline__ void load_tile(const uint4* __restrict__ Ablk,
                                          const uint4* __restrict__ Bblk,
                                          char* stage, int tid) {
    uint32_t sb = (uint32_t)__cvta_generic_to_shared(stage);
    #pragma unroll
    for (int i = 0; i < 4; i++)
        cp_async16(sb + (tid + i * THREADS) * 16, Ablk + tid + i * THREADS);
    #pragma unroll
    for (int i = 0; i < 4; i++)
        cp_async16(sb + (tid + (4 + i) * THREADS) * 16, Bblk + tid + i * THREADS);
}

__global__ void __launch_bounds__(THREADS, 2)
fp8linear_hmma_kernel(const float* __restrict__ BIAS,
                      float* __restrict__ OUT) {
    const int tid = threadIdx.x;
    const int lane = tid & 31;
    const int wid = tid >> 5;      // 0..3
    const int wm = wid & 1;        // 2 x 64 rows
    const int wn = wid >> 1;       // 2 x 64 cols (8 n8-tiles)
    const int g = lane >> 2;
    const int tig = lane & 3;

    // rasterization: GROUP_M=16
    int pid = blockIdx.x;
    int group = pid >> 11;
    int pid_loc = pid & 2047;
    int pid_m = group * 16 + (pid_loc & 15);
    int pid_n = pid_loc >> 4;

    const uint4* Abase = Xp + (size_t)pid_m * 65536;   // 512 uint4 per kt
    const uint4* Bbase = Wp + (size_t)pid_n * 65536;

    float acc[4][8][4];
    #pragma unroll
    for (int i = 0; i < 4; i++)
        #pragma unroll
        for (int j = 0; j < 8; j++)
            #pragma unroll
            for (int q = 0; q < 4; q++) acc[i][j][q] = 0.0f;

    #pragma unroll
    for (int p = 0; p < 5; p++) {
        load_tile(Abase + p * 512, Bbase + p * 512,
                  smem_raw + p * STAGE_BYTES, tid);
        CP_COMMIT();
    }

    for (int kt = 0; kt < NKT; kt++) {
        CP_WAIT4();
        __syncthreads();
        if (kt + 5 < NKT)
            load_tile(Abase + (kt + 5) * 512, Bbase + (kt + 5) * 512,
                      smem_raw + ((kt + 5) % NSTAGES) * STAGE_BYTES, tid);
        CP_COMMIT();

        const char* stg = smem_raw + (kt % NSTAGES) * STAGE_BYTES;
        const uint4* As = (const uint4*)stg;                 // 512 chunks
        const uint4* Bs = (const uint4*)(stg + 8192);

        // B fragments: 8 n8-tiles, one v4 covers both k16 halves
        uint4 bfr[8];
        #pragma unroll
        for (int j = 0; j < 8; j++)
            bfr[j] = Bs[(wn * 8 + j) * 32 + lane];

        #pragma unroll
        for (int s = 0; s < 2; s++) {
            uint4 afr[4];
            #pragma unroll
            for (int i = 0; i < 4; i++)
                afr[i] = As[((wm * 4 + i) * 2 + s) * 32 + lane];
            #pragma unroll
            for (int i = 0; i < 4; i++) {
                #pragma unroll
                for (int j = 0; j < 8; j++) {
                    uint32_t b0 = s ? bfr[j].z : bfr[j].x;
                    uint32_t b1 = s ? bfr[j].w : bfr[j].y;
                    mma_f16(acc[i][j], (const uint32_t*)&afr[i], b0, b1);
                }
            }
        }
    }

    // ---------------- epilogue: bias + store ----------------
    #pragma unroll
    for (int j = 0; j < 8; j++) {
        int col = pid_n * TN + wn * 64 + j * 8 + tig * 2;
        float2 bb = *(const float2*)(BIAS + col);
        #pragma unroll
        for (int i = 0; i < 4; i++) {
            int row0 = pid_m * TM + wm * 64 + i * 16 + g;
            float2 o0, o1;
            o0.x = acc[i][j][0] + bb.x;
            o0.y = acc[i][j][1] + bb.y;
            o1.x = acc[i][j][2] + bb.x;
            o1.y = acc[i][j][3] + bb.y;
            *(float2*)(OUT + (size_t)row0 * N_ALL + col) = o0;
            *(float2*)(OUT + (size_t)(row0 + 8) * N_ALL + col) = o1;
        }
    }
}

// ---------------- launch ----------------
extern "C" void kernel_launch(void* const* d_in, const int* in_sizes, int n_in,
                              void* d_out, int out_size) {
    const float* x = (const float*)d_in[0];      // [4,2048,4096]
    const float* qw = (const float*)d_in[1];     // [16384,4096]
    const float* sc = (const float*)d_in[2];     // [16384,32]
    const float* bias = (const float*)d_in[3];   // [16384]
    float* out = (float*)d_out;                  // [4,2048,16384]

    prep_x_kernel<<<4194304 / 256, 256>>>(x);
    prep_w_kernel<<<8388608 / 256, 256>>>(qw, sc);

    cudaFuncSetAttribute(fp8linear_hmma_kernel,
                         cudaFuncAttributeMaxDynamicSharedMemorySize, SMEM_TOTAL);
    int grid = (M_ALL / TM) * (N_ALL / TN);      // 8192
    fp8linear_hmma_kernel<<<grid, THREADS, SMEM_TOTAL>>>(bias, out);
}

// round 10
// speedup vs baseline: 1.4250x; 1.0451x over previous
#include <cuda_runtime.h>
#include <cuda_fp16.h>
#include <cstdint>

// ---------------------------------------------------------------------------
// FP8Linear: out[M,N] = x[M,K] @ (qweight*scales)^T + bias
// M=8192, N=16384, K=4096, group=128.
// R10: persistent CTAs (grid=304, tile stride 304) over the exact R5 inner
// loop (CTA 128x128, 4 warps, 64x64 warp tile, TK=32, 4 stages, wait_group 2).
// Load cursor runs 3 k-steps ahead ACROSS tile boundaries: at kt=125..127 it
// fetches the next tile's stages, so the cp.async pipe never drains and the
// epilogue overlaps the next tile's prologue. Stage = kt&3 (128 % 4 == 0).
// ---------------------------------------------------------------------------

#define M_ALL 8192
#define N_ALL 16384
#define K_ALL 4096
#define TM 128
#define TN 128
#define TK 32
#define THREADS 128
#define NKT (K_ALL / TK)              // 128
#define NSTAGES 4
#define STAGE_BYTES 16384             // A 8KB + B 8KB (fp16)
#define SMEM_TOTAL (NSTAGES * STAGE_BYTES)  // 65536
#define NTILES 8192
#define GRID 304                      // 2 CTAs x 152 SMs

// Packed operand scratch (fragment-major, fp16) -- layout unchanged since R4.
// A' chunk (mb,kt,it,s,lane): regs x/y/z/w = {m=g,k0},{m=g+8,k0},{m=g,k0+8},{m=g+8,k0+8}
//   chunk id = mb*65536 + kt*512 + it*64 + s*32 + lane
// B' chunk (nb,kt,jt,lane):   regs x/y/z/w = (s0,r0),(s0,r1),(s1,r0),(s1,r1)
//   chunk id = nb*65536 + kt*512 + jt*32 + lane
__device__ uint4 Xp[64ull * 128 * 8 * 2 * 32];     //  64 MB
__device__ uint4 Wp[128ull * 128 * 16 * 32];       // 128 MB

// ---------------- helpers ----------------
__device__ __forceinline__ void cp_async16(uint32_t smem_dst, const void* gsrc) {
    asm volatile("cp.async.cg.shared.global [%0], [%1], 16;"
                 :: "r"(smem_dst), "l"(__cvta_generic_to_global(gsrc))
                 : "memory");
}
#define CP_COMMIT() asm volatile("cp.async.commit_group;" ::: "memory")
#define CP_WAIT2()  asm volatile("cp.async.wait_group 2;" ::: "memory")

__device__ __forceinline__ void mma_f16(float* c, const uint32_t* a,
                                        uint32_t b0, uint32_t b1) {
    asm volatile(
        "mma.sync.aligned.m16n8k16.row.col.f32.f16.f16.f32 "
        "{%0,%1,%2,%3}, {%4,%5,%6,%7}, {%8,%9}, {%0,%1,%2,%3};"
        : "+f"(c[0]), "+f"(c[1]), "+f"(c[2]), "+f"(c[3])
        : "r"(a[0]), "r"(a[1]), "r"(a[2]), "r"(a[3]), "r"(b0), "r"(b1));
}

__device__ __forceinline__ uint32_t h2(float lo, float hi) {
    __half2 h = __floats2half2_rn(lo, hi);
    return *(uint32_t*)&h;
}

// tile pid -> operand bases (GROUP_M=16 rasterization, unchanged)
__device__ __forceinline__ void tile_coords(int pid, int* pm, int* pn) {
    int group = pid >> 11;
    int loc = pid & 2047;
    *pm = group * 16 + (loc & 15);
    *pn = loc >> 4;
}

// ---------------- prep kernels (unchanged) ----------------
// cid fields: lane[0:5) s[5] it[6:9) kt[9:16) mb[16:22)
__global__ void __launch_bounds__(256)
prep_x_kernel(const float* __restrict__ X) {
    uint32_t cid = blockIdx.x * 256 + threadIdx.x;
    int lane = cid & 31;
    int s    = (cid >> 5) & 1;
    int it   = (cid >> 6) & 7;
    int kt   = (cid >> 9) & 127;
    int mb   = cid >> 16;
    int g = lane >> 2, tig = lane & 3;
    int m0 = mb * 128 + it * 16 + g;
    int k0 = kt * 32 + s * 16 + 2 * tig;
    const float* p0 = X + (size_t)m0 * K_ALL + k0;
    const float* p1 = X + (size_t)(m0 + 8) * K_ALL + k0;
    float2 v0 = *(const float2*)(p0);
    float2 v1 = *(const float2*)(p1);
    float2 v2 = *(const float2*)(p0 + 8);
    float2 v3 = *(const float2*)(p1 + 8);
    uint4 out;
    out.x = h2(v0.x, v0.y);
    out.y = h2(v1.x, v1.y);
    out.z = h2(v2.x, v2.y);
    out.w = h2(v3.x, v3.y);
    Xp[cid] = out;
}

// cid fields: lane[0:5) jt[5:9) kt[9:16) nb[16:23)
__global__ void __launch_bounds__(256)
prep_w_kernel(const float* __restrict__ W, const float* __restrict__ S) {
    uint32_t cid = blockIdx.x * 256 + threadIdx.x;
    int lane = cid & 31;
    int jt   = (cid >> 5) & 15;
    int kt   = (cid >> 9) & 127;
    int nb   = cid >> 16;
    int g = lane >> 2, tig = lane & 3;
    int n  = nb * 128 + jt * 8 + g;
    int kb = kt * 32 + 2 * tig;
    float sc = __ldg(S + (size_t)n * 32 + (kt >> 2));
    const float* p = W + (size_t)n * K_ALL + kb;
    float2 v0 = *(const float2*)(p);
    float2 v1 = *(const float2*)(p + 8);
    float2 v2 = *(const float2*)(p + 16);
    float2 v3 = *(const float2*)(p + 24);
    uint4 out;
    out.x = h2(v0.x * sc, v0.y * sc);
    out.y = h2(v1.x * sc, v1.y * sc);
    out.z = h2(v2.x * sc, v2.y * sc);
    out.w = h2(v3.x * sc, v3.y * sc);
    Wp[cid] = out;
}

// ---------------- GEMM ----------------
extern __shared__ __align__(1024) char smem_raw[];

__device__ __forceinline__ void load_tile(const uint4* __restrict__ Ablk,
                                          const uint4* __restrict__ Bblk,
                                          char* stage, int tid) {
    uint32_t sb = (uint32_t)__cvta_generic_to_shared(stage);
    #pragma unroll
    for (int i = 0; i < 4; i++)
        cp_async16(sb + (tid + i * THREADS) * 16, Ablk + tid + i * THREADS);
    #pragma unroll
    for (int i = 0; i < 4; i++)
        cp_async16(sb + (tid + (4 + i) * THREADS) * 16, Bblk + tid + i * THREADS);
}

__global__ void __launch_bounds__(THREADS, 2)
fp8linear_hmma_kernel(const float* __restrict__ BIAS,
                      float* __restrict__ OUT) {
    const int tid = threadIdx.x;
    const int lane = tid & 31;
    const int wid = tid >> 5;      // 0..3
    const int wm = wid & 1;        // 2 x 64 rows
    const int wn = wid >> 1;       // 2 x 64 cols (8 n8-tiles)
    const int g = lane >> 2;
    const int tig = lane & 3;

    // ---- load cursor (runs 3 k-steps ahead, across tiles) ----
    int ltile = blockIdx.x;
    int lkt = 0;
    int lm, ln;
    tile_coords(ltile, &lm, &ln);
    const uint4* Al = Xp + (size_t)lm * 65536;
    const uint4* Bl = Wp + (size_t)ln * 65536;

    // prologue: stages 0..2 (lkt 0..2 of first tile)
    #pragma unroll
    for (int p = 0; p < 3; p++) {
        load_tile(Al + lkt * 512, Bl + lkt * 512,
                  smem_raw + p * STAGE_BYTES, tid);
        CP_COMMIT();
        lkt++;
    }

    float acc[4][8][4];

    for (int ptile = blockIdx.x; ptile < NTILES; ptile += GRID) {
        int pid_m, pid_n;
        tile_coords(ptile, &pid_m, &pid_n);

        #pragma unroll
        for (int i = 0; i < 4; i++)
            #pragma unroll
            for (int j = 0; j < 8; j++)
                #pragma unroll
                for (int q = 0; q < 4; q++) acc[i][j][q] = 0.0f;

        for (int kt = 0; kt < NKT; kt++) {
            CP_WAIT2();
            __syncthreads();

            // produce: step kt+3 of the load stream (rolls into next tile)
            if (lkt == NKT) {
                lkt = 0;
                ltile += GRID;
                if (ltile < NTILES) {
                    tile_coords(ltile, &lm, &ln);
                    Al = Xp + (size_t)lm * 65536;
                    Bl = Wp + (size_t)ln * 65536;
                }
            }
            if (ltile < NTILES)
                load_tile(Al + lkt * 512, Bl + lkt * 512,
                          smem_raw + ((kt + 3) & 3) * STAGE_BYTES, tid);
            CP_COMMIT();
            lkt++;

            // consume stage kt&3
            const char* stg = smem_raw + (kt & 3) * STAGE_BYTES;
            const uint4* As = (const uint4*)stg;
            const uint4* Bs = (const uint4*)(stg + 8192);

            uint4 bfr[8];
            #pragma unroll
            for (int j = 0; j < 8; j++)
                bfr[j] = Bs[(wn * 8 + j) * 32 + lane];

            #pragma unroll
            for (int s = 0; s < 2; s++) {
                uint4 afr[4];
                #pragma unroll
                for (int i = 0; i < 4; i++)
                    afr[i] = As[((wm * 4 + i) * 2 + s) * 32 + lane];
                #pragma unroll
                for (int i = 0; i < 4; i++) {
                    #pragma unroll
                    for (int j = 0; j < 8; j++) {
                        uint32_t b0 = s ? bfr[j].z : bfr[j].x;
                        uint32_t b1 = s ? bfr[j].w : bfr[j].y;
                        mma_f16(acc[i][j], (const uint32_t*)&afr[i], b0, b1);
                    }
                }
            }
        }

        // ---- epilogue (overlaps next tile's in-flight prologue loads) ----
        #pragma unroll
        for (int j = 0; j < 8; j++) {
            int col = pid_n * TN + wn * 64 + j * 8 + tig * 2;
            float2 bb = *(const float2*)(BIAS + col);
            #pragma unroll
            for (int i = 0; i < 4; i++) {
                int row0 = pid_m * TM + wm * 64 + i * 16 + g;
                float2 o0, o1;
                o0.x = acc[i][j][0] + bb.x;
                o0.y = acc[i][j][1] + bb.y;
                o1.x = acc[i][j][2] + bb.x;
                o1.y = acc[i][j][3] + bb.y;
                *(float2*)(OUT + (size_t)row0 * N_ALL + col) = o0;
                *(float2*)(OUT + (size_t)(row0 + 8) * N_ALL + col) = o1;
            }
        }
    }
}

// ---------------- launch ----------------
extern "C" void kernel_launch(void* const* d_in, const int* in_sizes, int n_in,
                              void* d_out, int out_size) {
    const float* x = (const float*)d_in[0];      // [4,2048,4096]
    const float* qw = (const float*)d_in[1];     // [16384,4096]
    const float* sc = (const float*)d_in[2];     // [16384,32]
    const float* bias = (const float*)d_in[3];   // [16384]
    float* out = (float*)d_out;                  // [4,2048,16384]

    prep_x_kernel<<<4194304 / 256, 256>>>(x);
    prep_w_kernel<<<8388608 / 256, 256>>>(qw, sc);

    cudaFuncSetAttribute(fp8linear_hmma_kernel,
                         cudaFuncAttributeMaxDynamicSharedMemorySize, SMEM_TOTAL);
    fp8linear_hmma_kernel<<<GRID, THREADS, SMEM_TOTAL>>>(bias, out);
}